// round 13
// baseline (speedup 1.0000x reference)
#include <cuda_runtime.h>
#include <cuda_fp16.h>
#include <cstdint>
#include <cstddef>

#define DEVINL __device__ __forceinline__

// ---------------- problem constants ----------------
static constexpr int BATCH = 16384;
static constexpr int DM    = 1024;
static constexpr int HID   = 2048;
static constexpr int NGRP  = 7;
static constexpr int G0K   = 512;
static constexpr int RK    = 256;
static constexpr int MT    = BATCH / 128;   // m-tiles per group

// ---------------- device scratch (static globals: allocation-free) ----------------
__device__ __half g_Xh  [(size_t)BATCH * 2048];
__device__ __half g_W1g0[(size_t)HID * G0K];
__device__ __half g_W3g0[(size_t)HID * G0K];
__device__ __half g_W1r [(size_t)6 * HID * RK];
__device__ __half g_W3r [(size_t)6 * HID * RK];
__device__ __half g_W2  [(size_t)NGRP * DM * HID];
__device__ __half g_Hs  [(size_t)NGRP * BATCH * HID];
__device__ __half g_tok [(size_t)NGRP * BATCH * DM];
__device__ float  g_ssq [(size_t)NGRP * BATCH];       // per-row sum of squares
__device__ unsigned g_cnt[(size_t)NGRP * MT];         // completion counters

// ---------------- helpers ----------------
DEVINL uint32_t smem_u32(const void* p) {
    uint32_t a;
    asm("{ .reg .u64 t; cvta.to.shared.u64 t, %1; cvt.u32.u64 %0, t; }" : "=r"(a) : "l"(p));
    return a;
}
DEVINL void cp16(uint32_t s, const void* g) {
    asm volatile("cp.async.cg.shared.global [%0], [%1], 16;" :: "r"(s), "l"(g) : "memory");
}
DEVINL void cp_commit() { asm volatile("cp.async.commit_group;" ::: "memory"); }

DEVINL uint32_t swz(uint32_t o) { return o ^ ((o >> 3) & 0x70); }

DEVINL void ldsm_x4(uint32_t* r, uint32_t addr) {
    asm volatile("ldmatrix.sync.aligned.m8n8.x4.shared.b16 {%0,%1,%2,%3}, [%4];"
                 : "=r"(r[0]), "=r"(r[1]), "=r"(r[2]), "=r"(r[3]) : "r"(addr));
}
DEVINL void mma16816(float* c, const uint32_t* a, const uint32_t* b) {
    asm volatile(
        "mma.sync.aligned.m16n8k16.row.col.f32.f16.f16.f32 "
        "{%0,%1,%2,%3}, {%4,%5,%6,%7}, {%8,%9}, {%0,%1,%2,%3};"
        : "+f"(c[0]), "+f"(c[1]), "+f"(c[2]), "+f"(c[3])
        : "r"(a[0]), "r"(a[1]), "r"(a[2]), "r"(a[3]), "r"(b[0]), "r"(b[1]));
}

// ---------------- single fused fp32 -> fp16 convert ----------------
struct CvtDesc {
    const float* src[7];
    __half*      dst[7];
    int          n4end[7];
};

__global__ void __launch_bounds__(256) cvt_all_kernel(CvtDesc d) {
    int i = blockIdx.x * blockDim.x + threadIdx.x;
    if (i >= d.n4end[6]) return;
    int seg = 0;
    while (i >= d.n4end[seg]) seg++;
    int base = (seg == 0) ? 0 : d.n4end[seg - 1];
    int j = i - base;
    float4 v = reinterpret_cast<const float4*>(d.src[seg])[j];
    __half2 a = __floats2half2_rn(v.x, v.y);
    __half2 c = __floats2half2_rn(v.z, v.w);
    uint2 o;
    o.x = *reinterpret_cast<uint32_t*>(&a);
    o.y = *reinterpret_cast<uint32_t*>(&c);
    reinterpret_cast<uint2*>(d.dst[seg])[j] = o;
}

// ================= phase 1: dual GEMM + SwiGLU =================
static constexpr int P1_NS   = 3;
static constexpr int P1_STG  = 32 * 1024;
static constexpr int P1_SMEM = P1_NS * P1_STG;

__global__ void __launch_bounds__(256, 2) phase1_kernel() {
    extern __shared__ char smem[];
    const uint32_t sbase = smem_u32(smem);
    const int tid = threadIdx.x;
    const int wid = tid >> 5, lane = tid & 31;
    const int wm = wid >> 1, wn = wid & 1;

    const int g   = blockIdx.z;
    const int nb0 = blockIdx.x * 64;
    const int m0  = blockIdx.y * 128;
    const int K   = (g == 0) ? G0K : RK;
    const int nch = K >> 6;
    const __half* Ap = g_Xh + (size_t)m0 * 2048 + (g == 0 ? 0 : G0K + (g - 1) * RK);
    const __half *B1p, *B3p;
    if (g == 0) {
        B1p = g_W1g0 + (size_t)nb0 * G0K;
        B3p = g_W3g0 + (size_t)nb0 * G0K;
    } else {
        size_t off = (size_t)(g - 1) * HID * RK + (size_t)nb0 * RK;
        B1p = g_W1r + off;
        B3p = g_W3r + off;
    }

    float accg[2][4][4];
    float accv[2][4][4];
#pragma unroll
    for (int im = 0; im < 2; im++)
#pragma unroll
        for (int in = 0; in < 4; in++)
#pragma unroll
            for (int q = 0; q < 4; q++) { accg[im][in][q] = 0.f; accv[im][in][q] = 0.f; }

    auto load_stage = [&](int s, int ch) {
        const uint32_t sb = sbase + (uint32_t)s * P1_STG;
        const int k0 = ch << 6;
#pragma unroll
        for (int j = 0; j < 4; j++) {
            int idx = j * 256 + tid;
            int r = idx >> 3, c = idx & 7;
            cp16(sb + swz((uint32_t)(r * 128 + c * 16)),
                 Ap + (size_t)r * 2048 + k0 + c * 8);
        }
#pragma unroll
        for (int j = 0; j < 2; j++) {
            int idx = j * 256 + tid;
            int r = idx >> 3, c = idx & 7;
            uint32_t so = swz((uint32_t)(r * 128 + c * 16));
            cp16(sb + 16384 + so, B1p + (size_t)r * K + k0 + c * 8);
            cp16(sb + 24576 + so, B3p + (size_t)r * K + k0 + c * 8);
        }
        cp_commit();
    };

    auto compute_stage = [&](int s) {
        const uint32_t sb = sbase + (uint32_t)s * P1_STG;
#pragma unroll
        for (int ks = 0; ks < 4; ks++) {
            uint32_t af[2][4];
#pragma unroll
            for (int im = 0; im < 2; im++) {
                int row = wm * 32 + im * 16 + (lane & 15);
                int kk  = ks * 16 + (lane >> 4) * 8;
                ldsm_x4(af[im], sb + swz((uint32_t)(row * 128 + kk * 2)));
            }
            uint32_t b1f[2][4], b3f[2][4];
#pragma unroll
            for (int bp = 0; bp < 2; bp++) {
                int nrow = wn * 32 + bp * 16 + ((lane >> 4) << 3) + (lane & 7);
                int kk   = ks * 16 + ((lane >> 3) & 1) * 8;
                uint32_t so = swz((uint32_t)(nrow * 128 + kk * 2));
                ldsm_x4(b1f[bp], sb + 16384 + so);
                ldsm_x4(b3f[bp], sb + 24576 + so);
            }
#pragma unroll
            for (int im = 0; im < 2; im++)
#pragma unroll
                for (int in = 0; in < 4; in++) {
                    const int bp = in >> 1, off = (in & 1) * 2;
                    mma16816(accg[im][in], af[im], &b1f[bp][off]);
                    mma16816(accv[im][in], af[im], &b3f[bp][off]);
                }
        }
    };

#pragma unroll
    for (int s = 0; s < P1_NS - 1; s++) {
        if (s < nch) load_stage(s, s); else cp_commit();
    }
    for (int i = 0; i < nch; i++) {
        asm volatile("cp.async.wait_group %0;" :: "n"(P1_NS - 2) : "memory");
        __syncthreads();
        const int nxt = i + P1_NS - 1;
        if (nxt < nch) load_stage(nxt % P1_NS, nxt); else cp_commit();
        compute_stage(i % P1_NS);
    }

    // epilogue: h = silu(gate) * val -> fp16
#pragma unroll
    for (int im = 0; im < 2; im++) {
        const int r0 = m0 + wm * 32 + im * 16 + (lane >> 2);
#pragma unroll
        for (int in = 0; in < 4; in++) {
            const int n = nb0 + wn * 32 + in * 8 + (lane & 3) * 2;
            float a0 = accg[im][in][0], a1 = accg[im][in][1];
            float a2 = accg[im][in][2], a3 = accg[im][in][3];
            float h0 = (a0 / (1.f + __expf(-a0))) * accv[im][in][0];
            float h1 = (a1 / (1.f + __expf(-a1))) * accv[im][in][1];
            float h2 = (a2 / (1.f + __expf(-a2))) * accv[im][in][2];
            float h3 = (a3 / (1.f + __expf(-a3))) * accv[im][in][3];
            *reinterpret_cast<__half2*>(g_Hs + ((size_t)g * BATCH + r0) * HID + n) =
                __floats2half2_rn(h0, h1);
            *reinterpret_cast<__half2*>(g_Hs + ((size_t)g * BATCH + r0 + 8) * HID + n) =
                __floats2half2_rn(h2, h3);
        }
    }
}

// ================= phase 2: tok = H @ W2^T + fused RMS-norm epilogue =================
// tile M=128 x N=128, 256 threads (8 warps 4x2, warp tile 32x64), NS=3, 2 CTAs/SM.
// The 8 N-tile CTAs of one (g, m-tile) cooperate: each contributes per-row sum-of-squares
// (fp32 accumulators) via atomics; the last-arriving CTA normalizes the L2-hot tok tile
// and writes the final output (replacing the separate norm kernel).
static constexpr int P2_NS   = 3;
static constexpr int P2_STG  = 32 * 1024;
static constexpr int P2_SMEM = P2_NS * P2_STG;

__global__ void __launch_bounds__(256, 2) phase2_kernel(const float* __restrict__ nw,
                                                        const float* __restrict__ nb,
                                                        const float* __restrict__ te,
                                                        float* __restrict__ out) {
    extern __shared__ char smem[];
    const uint32_t sbase = smem_u32(smem);
    const int tid = threadIdx.x;
    const int wid = tid >> 5, lane = tid & 31;
    const int wm = wid >> 1, wn = wid & 1;

    const int g   = blockIdx.z;
    const int nb0 = blockIdx.x * 128;
    const int m0  = blockIdx.y * 128;
    const int nch = HID >> 6;  // 32
    const __half* Ap = g_Hs + ((size_t)g * BATCH + m0) * HID;
    const __half* Bp = g_W2 + ((size_t)g * DM + nb0) * HID;

    float acc[2][8][4];
#pragma unroll
    for (int im = 0; im < 2; im++)
#pragma unroll
        for (int in = 0; in < 8; in++)
#pragma unroll
            for (int q = 0; q < 4; q++) acc[im][in][q] = 0.f;

    auto load_stage = [&](int s, int ch) {
        const uint32_t sb = sbase + (uint32_t)s * P2_STG;
        const int k0 = ch << 6;
#pragma unroll
        for (int j = 0; j < 4; j++) {
            int idx = j * 256 + tid;
            int r = idx >> 3, c = idx & 7;
            cp16(sb + swz((uint32_t)(r * 128 + c * 16)),
                 Ap + (size_t)r * HID + k0 + c * 8);
        }
#pragma unroll
        for (int j = 0; j < 4; j++) {
            int idx = j * 256 + tid;
            int r = idx >> 3, c = idx & 7;
            cp16(sb + 16384 + swz((uint32_t)(r * 128 + c * 16)),
                 Bp + (size_t)r * HID + k0 + c * 8);
        }
        cp_commit();
    };

    auto compute_stage = [&](int s) {
        const uint32_t sb = sbase + (uint32_t)s * P2_STG;
#pragma unroll
        for (int ks = 0; ks < 4; ks++) {
            uint32_t af[2][4];
#pragma unroll
            for (int im = 0; im < 2; im++) {
                int row = wm * 32 + im * 16 + (lane & 15);
                int kk  = ks * 16 + (lane >> 4) * 8;
                ldsm_x4(af[im], sb + swz((uint32_t)(row * 128 + kk * 2)));
            }
            uint32_t bf[4][4];
#pragma unroll
            for (int bp = 0; bp < 4; bp++) {
                int nrow = wn * 64 + bp * 16 + ((lane >> 4) << 3) + (lane & 7);
                int kk   = ks * 16 + ((lane >> 3) & 1) * 8;
                ldsm_x4(bf[bp], sb + 16384 + swz((uint32_t)(nrow * 128 + kk * 2)));
            }
#pragma unroll
            for (int im = 0; im < 2; im++)
#pragma unroll
                for (int in = 0; in < 8; in++) {
                    const int bp = in >> 1, off = (in & 1) * 2;
                    mma16816(acc[im][in], af[im], &bf[bp][off]);
                }
        }
    };

#pragma unroll
    for (int s = 0; s < P2_NS - 1; s++) load_stage(s, s);
    for (int i = 0; i < nch; i++) {
        asm volatile("cp.async.wait_group %0;" :: "n"(P2_NS - 2) : "memory");
        __syncthreads();
        const int nxt = i + P2_NS - 1;
        if (nxt < nch) load_stage(nxt % P2_NS, nxt); else cp_commit();
        compute_stage(i % P2_NS);
    }

    // ---- epilogue: fp16 tok stores + per-row sum-of-squares (fp32 accum) ----
    float rs[2][2] = {{0.f, 0.f}, {0.f, 0.f}};   // [im][half: r0 / r0+8]
#pragma unroll
    for (int im = 0; im < 2; im++) {
        const int r0 = m0 + wm * 32 + im * 16 + (lane >> 2);
#pragma unroll
        for (int in = 0; in < 8; in++) {
            const int n = nb0 + wn * 64 + in * 8 + (lane & 3) * 2;
            float a0 = acc[im][in][0], a1 = acc[im][in][1];
            float a2 = acc[im][in][2], a3 = acc[im][in][3];
            rs[im][0] += a0 * a0 + a1 * a1;
            rs[im][1] += a2 * a2 + a3 * a3;
            __half* t0 = g_tok + ((size_t)g * BATCH + r0) * DM + n;
            __half* t1 = g_tok + ((size_t)g * BATCH + r0 + 8) * DM + n;
            *reinterpret_cast<__half2*>(t0) = __floats2half2_rn(a0, a1);
            *reinterpret_cast<__half2*>(t1) = __floats2half2_rn(a2, a3);
        }
    }
#pragma unroll
    for (int im = 0; im < 2; im++)
#pragma unroll
        for (int h = 0; h < 2; h++) {
            float v = rs[im][h];
            v += __shfl_xor_sync(0xffffffffu, v, 1);
            v += __shfl_xor_sync(0xffffffffu, v, 2);
            if ((lane & 3) == 0) {
                int row = m0 + wm * 32 + im * 16 + h * 8 + (lane >> 2);
                atomicAdd(&g_ssq[(size_t)g * BATCH + row], v);
            }
        }

    // ---- completion counter; last CTA normalizes the tile ----
    __threadfence();
    __syncthreads();
    __shared__ int s_last;
    if (tid == 0) {
        unsigned old = atomicAdd(&g_cnt[(size_t)g * MT + blockIdx.y], 1u);
        s_last = (old == (DM / 128) - 1) ? 1 : 0;
    }
    __syncthreads();
    if (s_last) {
        __threadfence();
        float* sinv = reinterpret_cast<float*>(smem);   // pipeline smem reused
        if (tid < 128) {
            float ss = __ldcg(&g_ssq[(size_t)g * BATCH + m0 + tid]);
            sinv[tid] = rsqrtf(ss * (1.0f / DM) + 1e-5f);
        }
        __syncthreads();
        // 128 rows x 1024 cols; 256 threads, each handles 128 groups of 4 cols
        for (int it = tid; it < 128 * 256; it += 256) {
            int r  = it >> 8;
            int c  = (it & 255) * 4;
            const __half* tp = g_tok + ((size_t)g * BATCH + m0 + r) * DM + c;
            uint2 raw = __ldcg(reinterpret_cast<const uint2*>(tp));
            __half2 p0 = *reinterpret_cast<__half2*>(&raw.x);
            __half2 p1 = *reinterpret_cast<__half2*>(&raw.y);
            float inv = sinv[r];
            float4 w  = *reinterpret_cast<const float4*>(nw + c);
            float4 bb = *reinterpret_cast<const float4*>(nb + c);
            float4 e  = *reinterpret_cast<const float4*>(te + (size_t)g * DM + c);
            float4 o;
            o.x = __half2float(__low2half(p0))  * inv * w.x + bb.x + e.x;
            o.y = __half2float(__high2half(p0)) * inv * w.y + bb.y + e.y;
            o.z = __half2float(__low2half(p1))  * inv * w.z + bb.z + e.z;
            o.w = __half2float(__high2half(p1)) * inv * w.w + bb.w + e.w;
            *reinterpret_cast<float4*>(out + ((size_t)(m0 + r) * NGRP + g) * DM + c) = o;
        }
    }
}

// ---------------- launch ----------------
extern "C" void kernel_launch(void* const* d_in, const int* in_sizes, int n_in,
                              void* d_out, int out_size) {
    const float* obs   = (const float*)d_in[0];
    const float* w1_g0 = (const float*)d_in[1];
    const float* w3_g0 = (const float*)d_in[2];
    const float* w2_g0 = (const float*)d_in[3];
    const float* w1_r  = (const float*)d_in[4];
    const float* w3_r  = (const float*)d_in[5];
    const float* w2_r  = (const float*)d_in[6];
    const float* nw    = (const float*)d_in[7];
    const float* nb    = (const float*)d_in[8];
    const float* te    = (const float*)d_in[9];
    float* out = (float*)d_out;

    void *p_Xh, *p_W1g0, *p_W3g0, *p_W1r, *p_W3r, *p_W2, *p_ssq, *p_cnt;
    cudaGetSymbolAddress(&p_Xh,   g_Xh);
    cudaGetSymbolAddress(&p_W1g0, g_W1g0);
    cudaGetSymbolAddress(&p_W3g0, g_W3g0);
    cudaGetSymbolAddress(&p_W1r,  g_W1r);
    cudaGetSymbolAddress(&p_W3r,  g_W3r);
    cudaGetSymbolAddress(&p_W2,   g_W2);
    cudaGetSymbolAddress(&p_ssq,  g_ssq);
    cudaGetSymbolAddress(&p_cnt,  g_cnt);

    cudaFuncSetAttribute(phase1_kernel, cudaFuncAttributeMaxDynamicSharedMemorySize, P1_SMEM);
    cudaFuncSetAttribute(phase2_kernel, cudaFuncAttributeMaxDynamicSharedMemorySize, P2_SMEM);

    // zero accumulators/counters (graph-capturable async memsets)
    cudaMemsetAsync(p_ssq, 0, (size_t)NGRP * BATCH * sizeof(float));
    cudaMemsetAsync(p_cnt, 0, (size_t)NGRP * MT * sizeof(unsigned));

    // Launch: ALL fp32->fp16 converts in one sweep
    {
        CvtDesc d;
        int n4[7];
        d.src[0] = obs;    d.dst[0] = (__half*)p_Xh;   n4[0] = (int)((size_t)BATCH * 2048 / 4);
        d.src[1] = w1_g0;  d.dst[1] = (__half*)p_W1g0; n4[1] = (int)((size_t)HID * G0K / 4);
        d.src[2] = w3_g0;  d.dst[2] = (__half*)p_W3g0; n4[2] = (int)((size_t)HID * G0K / 4);
        d.src[3] = w1_r;   d.dst[3] = (__half*)p_W1r;  n4[3] = (int)((size_t)6 * HID * RK / 4);
        d.src[4] = w3_r;   d.dst[4] = (__half*)p_W3r;  n4[4] = (int)((size_t)6 * HID * RK / 4);
        d.src[5] = w2_g0;  d.dst[5] = (__half*)p_W2;   n4[5] = (int)((size_t)DM * HID / 4);
        d.src[6] = w2_r;
        d.dst[6] = (__half*)((char*)p_W2 + (size_t)DM * HID * sizeof(__half));
        n4[6] = (int)((size_t)6 * DM * HID / 4);
        int acc = 0;
        for (int s = 0; s < 7; s++) { acc += n4[s]; d.n4end[s] = acc; }
        cvt_all_kernel<<<(acc + 255) / 256, 256>>>(d);
    }
    // phase 1
    {
        dim3 grid(HID / 64, BATCH / 128, NGRP);
        phase1_kernel<<<grid, 256, P1_SMEM>>>();
    }
    // phase 2 (+ fused norm)
    {
        dim3 grid(DM / 128, BATCH / 128, NGRP);
        phase2_kernel<<<grid, 256, P2_SMEM>>>(nw, nb, te, out);
    }
    (void)in_sizes; (void)n_in; (void)out_size;
}

// round 14
// speedup vs baseline: 1.1420x; 1.1420x over previous
#include <cuda_runtime.h>
#include <cuda_fp16.h>
#include <cstdint>
#include <cstddef>

#define DEVINL __device__ __forceinline__

// ---------------- problem constants ----------------
static constexpr int BATCH = 16384;
static constexpr int DM    = 1024;
static constexpr int HID   = 2048;
static constexpr int NGRP  = 7;
static constexpr int G0K   = 512;
static constexpr int RK    = 256;

// ---------------- device scratch (static globals: allocation-free) ----------------
__device__ __half g_Xh  [(size_t)BATCH * 2048];        // fp16 obs
__device__ __half g_W1g0[(size_t)HID * G0K];
__device__ __half g_W3g0[(size_t)HID * G0K];
__device__ __half g_W1r [(size_t)6 * HID * RK];
__device__ __half g_W3r [(size_t)6 * HID * RK];
__device__ __half g_W2  [(size_t)NGRP * DM * HID];     // [g][d][h]
__device__ __half g_Hs  [(size_t)NGRP * BATCH * HID];  // [g][b][h] swiglu output
__device__ __half g_tok [(size_t)NGRP * BATCH * DM];   // [g][b][d] pre-norm tokens (fp16)

// ---------------- helpers ----------------
DEVINL uint32_t smem_u32(const void* p) {
    uint32_t a;
    asm("{ .reg .u64 t; cvta.to.shared.u64 t, %1; cvt.u32.u64 %0, t; }" : "=r"(a) : "l"(p));
    return a;
}
DEVINL void cp16(uint32_t s, const void* g) {
    asm volatile("cp.async.cg.shared.global [%0], [%1], 16;" :: "r"(s), "l"(g) : "memory");
}
DEVINL void cp_commit() { asm volatile("cp.async.commit_group;" ::: "memory"); }

DEVINL uint32_t swz(uint32_t o) { return o ^ ((o >> 3) & 0x70); }

DEVINL void ldsm_x4(uint32_t* r, uint32_t addr) {
    asm volatile("ldmatrix.sync.aligned.m8n8.x4.shared.b16 {%0,%1,%2,%3}, [%4];"
                 : "=r"(r[0]), "=r"(r[1]), "=r"(r[2]), "=r"(r[3]) : "r"(addr));
}
DEVINL void mma16816(float* c, const uint32_t* a, const uint32_t* b) {
    asm volatile(
        "mma.sync.aligned.m16n8k16.row.col.f32.f16.f16.f32 "
        "{%0,%1,%2,%3}, {%4,%5,%6,%7}, {%8,%9}, {%0,%1,%2,%3};"
        : "+f"(c[0]), "+f"(c[1]), "+f"(c[2]), "+f"(c[3])
        : "r"(a[0]), "r"(a[1]), "r"(a[2]), "r"(a[3]), "r"(b[0]), "r"(b[1]));
}

// ---------------- single fused fp32 -> fp16 convert (ALL tensors, 1 launch) ----------------
struct CvtDesc {
    const float* src[7];
    __half*      dst[7];
    int          n4end[7];   // inclusive prefix sums of n/4
};

__global__ void __launch_bounds__(256) cvt_all_kernel(CvtDesc d) {
    int i = blockIdx.x * blockDim.x + threadIdx.x;
    if (i >= d.n4end[6]) return;
    int seg = 0;
    while (i >= d.n4end[seg]) seg++;
    int base = (seg == 0) ? 0 : d.n4end[seg - 1];
    int j = i - base;
    float4 v = reinterpret_cast<const float4*>(d.src[seg])[j];
    __half2 a = __floats2half2_rn(v.x, v.y);
    __half2 c = __floats2half2_rn(v.z, v.w);
    uint2 o;
    o.x = *reinterpret_cast<uint32_t*>(&a);
    o.y = *reinterpret_cast<uint32_t*>(&c);
    reinterpret_cast<uint2*>(d.dst[seg])[j] = o;
}

// ================= phase 1: dual GEMM + SwiGLU =================
// tile M=128 x N=64 (of HIDDEN), dual accum (W1 & W3). 256 threads, 8 warps 4x2.
// K-chunk 64. Stage = A 16KB + B1 8KB + B3 8KB = 32KB. 3 stages -> 96KB -> 2 CTAs/SM.
static constexpr int P1_NS   = 3;
static constexpr int P1_STG  = 32 * 1024;
static constexpr int P1_SMEM = P1_NS * P1_STG;

__global__ void __launch_bounds__(256, 2) phase1_kernel() {
    extern __shared__ char smem[];
    const uint32_t sbase = smem_u32(smem);
    const int tid = threadIdx.x;
    const int wid = tid >> 5, lane = tid & 31;
    const int wm = wid >> 1, wn = wid & 1;

    const int g   = blockIdx.z;
    const int nb0 = blockIdx.x * 64;
    const int m0  = blockIdx.y * 128;
    const int K   = (g == 0) ? G0K : RK;
    const int nch = K >> 6;
    const __half* Ap = g_Xh + (size_t)m0 * 2048 + (g == 0 ? 0 : G0K + (g - 1) * RK);
    const __half *B1p, *B3p;
    if (g == 0) {
        B1p = g_W1g0 + (size_t)nb0 * G0K;
        B3p = g_W3g0 + (size_t)nb0 * G0K;
    } else {
        size_t off = (size_t)(g - 1) * HID * RK + (size_t)nb0 * RK;
        B1p = g_W1r + off;
        B3p = g_W3r + off;
    }

    float accg[2][4][4];
    float accv[2][4][4];
#pragma unroll
    for (int im = 0; im < 2; im++)
#pragma unroll
        for (int in = 0; in < 4; in++)
#pragma unroll
            for (int q = 0; q < 4; q++) { accg[im][in][q] = 0.f; accv[im][in][q] = 0.f; }

    auto load_stage = [&](int s, int ch) {
        const uint32_t sb = sbase + (uint32_t)s * P1_STG;
        const int k0 = ch << 6;
#pragma unroll
        for (int j = 0; j < 4; j++) {                 // A: 128x64
            int idx = j * 256 + tid;
            int r = idx >> 3, c = idx & 7;
            cp16(sb + swz((uint32_t)(r * 128 + c * 16)),
                 Ap + (size_t)r * 2048 + k0 + c * 8);
        }
#pragma unroll
        for (int j = 0; j < 2; j++) {                 // B1/B3: 64x64 each
            int idx = j * 256 + tid;
            int r = idx >> 3, c = idx & 7;
            uint32_t so = swz((uint32_t)(r * 128 + c * 16));
            cp16(sb + 16384 + so, B1p + (size_t)r * K + k0 + c * 8);
            cp16(sb + 24576 + so, B3p + (size_t)r * K + k0 + c * 8);
        }
        cp_commit();
    };

    auto compute_stage = [&](int s) {
        const uint32_t sb = sbase + (uint32_t)s * P1_STG;
#pragma unroll
        for (int ks = 0; ks < 4; ks++) {
            uint32_t af[2][4];
#pragma unroll
            for (int im = 0; im < 2; im++) {
                int row = wm * 32 + im * 16 + (lane & 15);
                int kk  = ks * 16 + (lane >> 4) * 8;
                ldsm_x4(af[im], sb + swz((uint32_t)(row * 128 + kk * 2)));
            }
            uint32_t b1f[2][4], b3f[2][4];
#pragma unroll
            for (int bp = 0; bp < 2; bp++) {
                int nrow = wn * 32 + bp * 16 + ((lane >> 4) << 3) + (lane & 7);
                int kk   = ks * 16 + ((lane >> 3) & 1) * 8;
                uint32_t so = swz((uint32_t)(nrow * 128 + kk * 2));
                ldsm_x4(b1f[bp], sb + 16384 + so);
                ldsm_x4(b3f[bp], sb + 24576 + so);
            }
#pragma unroll
            for (int im = 0; im < 2; im++)
#pragma unroll
                for (int in = 0; in < 4; in++) {
                    const int bp = in >> 1, off = (in & 1) * 2;
                    mma16816(accg[im][in], af[im], &b1f[bp][off]);
                    mma16816(accv[im][in], af[im], &b3f[bp][off]);
                }
        }
    };

#pragma unroll
    for (int s = 0; s < P1_NS - 1; s++) {
        if (s < nch) load_stage(s, s); else cp_commit();
    }
    for (int i = 0; i < nch; i++) {
        asm volatile("cp.async.wait_group %0;" :: "n"(P1_NS - 2) : "memory");
        __syncthreads();
        const int nxt = i + P1_NS - 1;
        if (nxt < nch) load_stage(nxt % P1_NS, nxt); else cp_commit();
        compute_stage(i % P1_NS);
    }

    // epilogue: h = silu(gate) * val -> fp16
#pragma unroll
    for (int im = 0; im < 2; im++) {
        const int r0 = m0 + wm * 32 + im * 16 + (lane >> 2);
#pragma unroll
        for (int in = 0; in < 4; in++) {
            const int n = nb0 + wn * 32 + in * 8 + (lane & 3) * 2;
            float a0 = accg[im][in][0], a1 = accg[im][in][1];
            float a2 = accg[im][in][2], a3 = accg[im][in][3];
            float h0 = (a0 / (1.f + __expf(-a0))) * accv[im][in][0];
            float h1 = (a1 / (1.f + __expf(-a1))) * accv[im][in][1];
            float h2 = (a2 / (1.f + __expf(-a2))) * accv[im][in][2];
            float h3 = (a3 / (1.f + __expf(-a3))) * accv[im][in][3];
            *reinterpret_cast<__half2*>(g_Hs + ((size_t)g * BATCH + r0) * HID + n) =
                __floats2half2_rn(h0, h1);
            *reinterpret_cast<__half2*>(g_Hs + ((size_t)g * BATCH + r0 + 8) * HID + n) =
                __floats2half2_rn(h2, h3);
        }
    }
}

// ================= phase 2: tok = H @ W2^T (fp16 out) =================
// tile M=128 x N=128 (of DM). 256 threads, 8 warps 4x2 (warp tile 32x64).
// K-chunk 64. Stage = A 16KB + B 16KB = 32KB. 3 stages -> 96KB -> 2 CTAs/SM.
static constexpr int P2_NS   = 3;
static constexpr int P2_STG  = 32 * 1024;
static constexpr int P2_SMEM = P2_NS * P2_STG;

__global__ void __launch_bounds__(256, 2) phase2_kernel() {
    extern __shared__ char smem[];
    const uint32_t sbase = smem_u32(smem);
    const int tid = threadIdx.x;
    const int wid = tid >> 5, lane = tid & 31;
    const int wm = wid >> 1, wn = wid & 1;

    const int g   = blockIdx.z;
    const int nb0 = blockIdx.x * 128;
    const int m0  = blockIdx.y * 128;
    const int nch = HID >> 6;  // 32
    const __half* Ap = g_Hs + ((size_t)g * BATCH + m0) * HID;
    const __half* Bp = g_W2 + ((size_t)g * DM + nb0) * HID;

    float acc[2][8][4];
#pragma unroll
    for (int im = 0; im < 2; im++)
#pragma unroll
        for (int in = 0; in < 8; in++)
#pragma unroll
            for (int q = 0; q < 4; q++) acc[im][in][q] = 0.f;

    auto load_stage = [&](int s, int ch) {
        const uint32_t sb = sbase + (uint32_t)s * P2_STG;
        const int k0 = ch << 6;
#pragma unroll
        for (int j = 0; j < 4; j++) {                 // A: 128x64
            int idx = j * 256 + tid;
            int r = idx >> 3, c = idx & 7;
            cp16(sb + swz((uint32_t)(r * 128 + c * 16)),
                 Ap + (size_t)r * HID + k0 + c * 8);
        }
#pragma unroll
        for (int j = 0; j < 4; j++) {                 // B: 128x64
            int idx = j * 256 + tid;
            int r = idx >> 3, c = idx & 7;
            cp16(sb + 16384 + swz((uint32_t)(r * 128 + c * 16)),
                 Bp + (size_t)r * HID + k0 + c * 8);
        }
        cp_commit();
    };

    auto compute_stage = [&](int s) {
        const uint32_t sb = sbase + (uint32_t)s * P2_STG;
#pragma unroll
        for (int ks = 0; ks < 4; ks++) {
            uint32_t af[2][4];
#pragma unroll
            for (int im = 0; im < 2; im++) {
                int row = wm * 32 + im * 16 + (lane & 15);
                int kk  = ks * 16 + (lane >> 4) * 8;
                ldsm_x4(af[im], sb + swz((uint32_t)(row * 128 + kk * 2)));
            }
            uint32_t bf[4][4];
#pragma unroll
            for (int bp = 0; bp < 4; bp++) {
                int nrow = wn * 64 + bp * 16 + ((lane >> 4) << 3) + (lane & 7);
                int kk   = ks * 16 + ((lane >> 3) & 1) * 8;
                ldsm_x4(bf[bp], sb + 16384 + swz((uint32_t)(nrow * 128 + kk * 2)));
            }
#pragma unroll
            for (int im = 0; im < 2; im++)
#pragma unroll
                for (int in = 0; in < 8; in++) {
                    const int bp = in >> 1, off = (in & 1) * 2;
                    mma16816(acc[im][in], af[im], &bf[bp][off]);
                }
        }
    };

#pragma unroll
    for (int s = 0; s < P2_NS - 1; s++) load_stage(s, s);
    for (int i = 0; i < nch; i++) {
        asm volatile("cp.async.wait_group %0;" :: "n"(P2_NS - 2) : "memory");
        __syncthreads();
        const int nxt = i + P2_NS - 1;
        if (nxt < nch) load_stage(nxt % P2_NS, nxt); else cp_commit();
        compute_stage(i % P2_NS);
    }

    // epilogue: fp16 tokens
#pragma unroll
    for (int im = 0; im < 2; im++) {
        const int r0 = m0 + wm * 32 + im * 16 + (lane >> 2);
#pragma unroll
        for (int in = 0; in < 8; in++) {
            const int n = nb0 + wn * 64 + in * 8 + (lane & 3) * 2;
            __half* t0 = g_tok + ((size_t)g * BATCH + r0) * DM + n;
            __half* t1 = g_tok + ((size_t)g * BATCH + r0 + 8) * DM + n;
            *reinterpret_cast<__half2*>(t0) = __floats2half2_rn(acc[im][in][0], acc[im][in][1]);
            *reinterpret_cast<__half2*>(t1) = __floats2half2_rn(acc[im][in][2], acc[im][in][3]);
        }
    }
}

// ---------------- phase 3: RMS norm + affine + term_embed -> out[b][g][d] ----------------
__global__ void __launch_bounds__(256) norm_kernel(const float* __restrict__ nw,
                                                   const float* __restrict__ nb,
                                                   const float* __restrict__ te,
                                                   float* __restrict__ out) {
    const int b = blockIdx.x;
    const int g = blockIdx.y;
    const int t = threadIdx.x;
    const __half* x = g_tok + ((size_t)g * BATCH + b) * DM;

    uint2 raw = __ldcs(reinterpret_cast<const uint2*>(x) + t);   // streaming: tok dead after this
    __half2 p0 = *reinterpret_cast<__half2*>(&raw.x);
    __half2 p1 = *reinterpret_cast<__half2*>(&raw.y);
    float4 v;
    v.x = __half2float(__low2half(p0));  v.y = __half2float(__high2half(p0));
    v.z = __half2float(__low2half(p1));  v.w = __half2float(__high2half(p1));

    float ss = v.x * v.x + v.y * v.y + v.z * v.z + v.w * v.w;
#pragma unroll
    for (int o = 16; o > 0; o >>= 1) ss += __shfl_xor_sync(0xffffffffu, ss, o);
    __shared__ float wsum[8];
    if ((t & 31) == 0) wsum[t >> 5] = ss;
    __syncthreads();
    float tot = wsum[0] + wsum[1] + wsum[2] + wsum[3] +
                wsum[4] + wsum[5] + wsum[6] + wsum[7];
    float inv = rsqrtf(tot * (1.0f / DM) + 1e-5f);

    float4 w = reinterpret_cast<const float4*>(nw)[t];
    float4 bb = reinterpret_cast<const float4*>(nb)[t];
    float4 e = reinterpret_cast<const float4*>(te + (size_t)g * DM)[t];
    float4 r;
    r.x = v.x * inv * w.x + bb.x + e.x;
    r.y = v.y * inv * w.y + bb.y + e.y;
    r.z = v.z * inv * w.z + bb.z + e.z;
    r.w = v.w * inv * w.w + bb.w + e.w;
    __stcs(reinterpret_cast<float4*>(out + ((size_t)b * NGRP + g) * DM) + t, r);  // streaming store
}

// ---------------- launch ----------------
extern "C" void kernel_launch(void* const* d_in, const int* in_sizes, int n_in,
                              void* d_out, int out_size) {
    const float* obs   = (const float*)d_in[0];
    const float* w1_g0 = (const float*)d_in[1];
    const float* w3_g0 = (const float*)d_in[2];
    const float* w2_g0 = (const float*)d_in[3];
    const float* w1_r  = (const float*)d_in[4];
    const float* w3_r  = (const float*)d_in[5];
    const float* w2_r  = (const float*)d_in[6];
    const float* nw    = (const float*)d_in[7];
    const float* nb    = (const float*)d_in[8];
    const float* te    = (const float*)d_in[9];
    float* out = (float*)d_out;

    void *p_Xh, *p_W1g0, *p_W3g0, *p_W1r, *p_W3r, *p_W2;
    cudaGetSymbolAddress(&p_Xh,   g_Xh);
    cudaGetSymbolAddress(&p_W1g0, g_W1g0);
    cudaGetSymbolAddress(&p_W3g0, g_W3g0);
    cudaGetSymbolAddress(&p_W1r,  g_W1r);
    cudaGetSymbolAddress(&p_W3r,  g_W3r);
    cudaGetSymbolAddress(&p_W2,   g_W2);

    cudaFuncSetAttribute(phase1_kernel, cudaFuncAttributeMaxDynamicSharedMemorySize, P1_SMEM);
    cudaFuncSetAttribute(phase2_kernel, cudaFuncAttributeMaxDynamicSharedMemorySize, P2_SMEM);

    // Launch #1: ALL fp32->fp16 converts in one sweep
    {
        CvtDesc d;
        int n4[7];
        d.src[0] = obs;    d.dst[0] = (__half*)p_Xh;   n4[0] = (int)((size_t)BATCH * 2048 / 4);
        d.src[1] = w1_g0;  d.dst[1] = (__half*)p_W1g0; n4[1] = (int)((size_t)HID * G0K / 4);
        d.src[2] = w3_g0;  d.dst[2] = (__half*)p_W3g0; n4[2] = (int)((size_t)HID * G0K / 4);
        d.src[3] = w1_r;   d.dst[3] = (__half*)p_W1r;  n4[3] = (int)((size_t)6 * HID * RK / 4);
        d.src[4] = w3_r;   d.dst[4] = (__half*)p_W3r;  n4[4] = (int)((size_t)6 * HID * RK / 4);
        d.src[5] = w2_g0;  d.dst[5] = (__half*)p_W2;   n4[5] = (int)((size_t)DM * HID / 4);
        d.src[6] = w2_r;
        d.dst[6] = (__half*)((char*)p_W2 + (size_t)DM * HID * sizeof(__half));
        n4[6] = (int)((size_t)6 * DM * HID / 4);
        int acc = 0;
        for (int s = 0; s < 7; s++) { acc += n4[s]; d.n4end[s] = acc; }
        cvt_all_kernel<<<(acc + 255) / 256, 256>>>(d);
    }
    // Launch #2: phase 1
    {
        dim3 grid(HID / 64, BATCH / 128, NGRP);
        phase1_kernel<<<grid, 256, P1_SMEM>>>();
    }
    // Launch #3: phase 2
    {
        dim3 grid(DM / 128, BATCH / 128, NGRP);
        phase2_kernel<<<grid, 256, P2_SMEM>>>();
    }
    // Launch #4: norm
    {
        dim3 grid(BATCH, NGRP);
        norm_kernel<<<grid, 256>>>(nw, nb, te, out);
    }
    (void)in_sizes; (void)n_in; (void)out_size;
}

// round 15
// speedup vs baseline: 1.1553x; 1.0116x over previous
#include <cuda_runtime.h>
#include <cuda_fp16.h>
#include <cstdint>
#include <cstddef>

#define DEVINL __device__ __forceinline__

// ---------------- problem constants ----------------
static constexpr int BATCH = 16384;
static constexpr int DM    = 1024;
static constexpr int HID   = 2048;
static constexpr int NGRP  = 7;
static constexpr int G0K   = 512;
static constexpr int RK    = 256;

// ---------------- device scratch (static globals: allocation-free) ----------------
__device__ __half g_Xh  [(size_t)BATCH * 2048];        // fp16 obs
__device__ __half g_W1g0[(size_t)HID * G0K];
__device__ __half g_W3g0[(size_t)HID * G0K];
__device__ __half g_W1r [(size_t)6 * HID * RK];
__device__ __half g_W3r [(size_t)6 * HID * RK];
__device__ __half g_W2  [(size_t)NGRP * DM * HID];     // [g][d][h]
__device__ __half g_Hs  [(size_t)NGRP * BATCH * HID];  // [g][b][h] swiglu output
__device__ __half g_tok [(size_t)NGRP * BATCH * DM];   // [g][b][d] pre-norm tokens (fp16)

// ---------------- helpers ----------------
DEVINL uint32_t smem_u32(const void* p) {
    uint32_t a;
    asm("{ .reg .u64 t; cvta.to.shared.u64 t, %1; cvt.u32.u64 %0, t; }" : "=r"(a) : "l"(p));
    return a;
}
DEVINL void cp16(uint32_t s, const void* g) {
    asm volatile("cp.async.cg.shared.global [%0], [%1], 16;" :: "r"(s), "l"(g) : "memory");
}
DEVINL void cp_commit() { asm volatile("cp.async.commit_group;" ::: "memory"); }

DEVINL uint32_t swz(uint32_t o) { return o ^ ((o >> 3) & 0x70); }

DEVINL void ldsm_x4(uint32_t* r, uint32_t addr) {
    asm volatile("ldmatrix.sync.aligned.m8n8.x4.shared.b16 {%0,%1,%2,%3}, [%4];"
                 : "=r"(r[0]), "=r"(r[1]), "=r"(r[2]), "=r"(r[3]) : "r"(addr));
}
DEVINL void mma16816(float* c, const uint32_t* a, const uint32_t* b) {
    asm volatile(
        "mma.sync.aligned.m16n8k16.row.col.f32.f16.f16.f32 "
        "{%0,%1,%2,%3}, {%4,%5,%6,%7}, {%8,%9}, {%0,%1,%2,%3};"
        : "+f"(c[0]), "+f"(c[1]), "+f"(c[2]), "+f"(c[3])
        : "r"(a[0]), "r"(a[1]), "r"(a[2]), "r"(a[3]), "r"(b[0]), "r"(b[1]));
}

// ---------------- single fused fp32 -> fp16 convert (ALL tensors, 1 launch) ----------------
struct CvtDesc {
    const float* src[7];
    __half*      dst[7];
    int          n4end[7];   // inclusive prefix sums of n/4
};

__global__ void __launch_bounds__(256) cvt_all_kernel(CvtDesc d) {
    int i = blockIdx.x * blockDim.x + threadIdx.x;
    if (i >= d.n4end[6]) return;
    int seg = 0;
    while (i >= d.n4end[seg]) seg++;
    int base = (seg == 0) ? 0 : d.n4end[seg - 1];
    int j = i - base;
    float4 v = reinterpret_cast<const float4*>(d.src[seg])[j];
    __half2 a = __floats2half2_rn(v.x, v.y);
    __half2 c = __floats2half2_rn(v.z, v.w);
    uint2 o;
    o.x = *reinterpret_cast<uint32_t*>(&a);
    o.y = *reinterpret_cast<uint32_t*>(&c);
    reinterpret_cast<uint2*>(d.dst[seg])[j] = o;
}

// ================= phase 1: dual GEMM + SwiGLU =================
// tile M=128 x N=64 (of HIDDEN), dual accum (W1 & W3). 256 threads, 8 warps 4x2.
// K-chunk 64. Stage = A 16KB + B1 8KB + B3 8KB = 32KB. 3 stages -> 96KB -> 2 CTAs/SM.
static constexpr int P1_NS   = 3;
static constexpr int P1_STG  = 32 * 1024;
static constexpr int P1_SMEM = P1_NS * P1_STG;

__global__ void __launch_bounds__(256, 2) phase1_kernel() {
    extern __shared__ char smem[];
    const uint32_t sbase = smem_u32(smem);
    const int tid = threadIdx.x;
    const int wid = tid >> 5, lane = tid & 31;
    const int wm = wid >> 1, wn = wid & 1;

    const int g   = blockIdx.z;
    const int nb0 = blockIdx.x * 64;
    const int m0  = blockIdx.y * 128;
    const int K   = (g == 0) ? G0K : RK;
    const int nch = K >> 6;
    const __half* Ap = g_Xh + (size_t)m0 * 2048 + (g == 0 ? 0 : G0K + (g - 1) * RK);
    const __half *B1p, *B3p;
    if (g == 0) {
        B1p = g_W1g0 + (size_t)nb0 * G0K;
        B3p = g_W3g0 + (size_t)nb0 * G0K;
    } else {
        size_t off = (size_t)(g - 1) * HID * RK + (size_t)nb0 * RK;
        B1p = g_W1r + off;
        B3p = g_W3r + off;
    }

    float accg[2][4][4];
    float accv[2][4][4];
#pragma unroll
    for (int im = 0; im < 2; im++)
#pragma unroll
        for (int in = 0; in < 4; in++)
#pragma unroll
            for (int q = 0; q < 4; q++) { accg[im][in][q] = 0.f; accv[im][in][q] = 0.f; }

    auto load_stage = [&](int s, int ch) {
        const uint32_t sb = sbase + (uint32_t)s * P1_STG;
        const int k0 = ch << 6;
#pragma unroll
        for (int j = 0; j < 4; j++) {                 // A: 128x64
            int idx = j * 256 + tid;
            int r = idx >> 3, c = idx & 7;
            cp16(sb + swz((uint32_t)(r * 128 + c * 16)),
                 Ap + (size_t)r * 2048 + k0 + c * 8);
        }
#pragma unroll
        for (int j = 0; j < 2; j++) {                 // B1/B3: 64x64 each
            int idx = j * 256 + tid;
            int r = idx >> 3, c = idx & 7;
            uint32_t so = swz((uint32_t)(r * 128 + c * 16));
            cp16(sb + 16384 + so, B1p + (size_t)r * K + k0 + c * 8);
            cp16(sb + 24576 + so, B3p + (size_t)r * K + k0 + c * 8);
        }
        cp_commit();
    };

    auto compute_stage = [&](int s) {
        const uint32_t sb = sbase + (uint32_t)s * P1_STG;
#pragma unroll
        for (int ks = 0; ks < 4; ks++) {
            uint32_t af[2][4];
#pragma unroll
            for (int im = 0; im < 2; im++) {
                int row = wm * 32 + im * 16 + (lane & 15);
                int kk  = ks * 16 + (lane >> 4) * 8;
                ldsm_x4(af[im], sb + swz((uint32_t)(row * 128 + kk * 2)));
            }
            uint32_t b1f[2][4], b3f[2][4];
#pragma unroll
            for (int bp = 0; bp < 2; bp++) {
                int nrow = wn * 32 + bp * 16 + ((lane >> 4) << 3) + (lane & 7);
                int kk   = ks * 16 + ((lane >> 3) & 1) * 8;
                uint32_t so = swz((uint32_t)(nrow * 128 + kk * 2));
                ldsm_x4(b1f[bp], sb + 16384 + so);
                ldsm_x4(b3f[bp], sb + 24576 + so);
            }
#pragma unroll
            for (int im = 0; im < 2; im++)
#pragma unroll
                for (int in = 0; in < 4; in++) {
                    const int bp = in >> 1, off = (in & 1) * 2;
                    mma16816(accg[im][in], af[im], &b1f[bp][off]);
                    mma16816(accv[im][in], af[im], &b3f[bp][off]);
                }
        }
    };

#pragma unroll
    for (int s = 0; s < P1_NS - 1; s++) {
        if (s < nch) load_stage(s, s); else cp_commit();
    }
    for (int i = 0; i < nch; i++) {
        asm volatile("cp.async.wait_group %0;" :: "n"(P1_NS - 2) : "memory");
        __syncthreads();
        const int nxt = i + P1_NS - 1;
        if (nxt < nch) load_stage(nxt % P1_NS, nxt); else cp_commit();
        compute_stage(i % P1_NS);
    }

    // epilogue: h = silu(gate) * val -> fp16
#pragma unroll
    for (int im = 0; im < 2; im++) {
        const int r0 = m0 + wm * 32 + im * 16 + (lane >> 2);
#pragma unroll
        for (int in = 0; in < 4; in++) {
            const int n = nb0 + wn * 32 + in * 8 + (lane & 3) * 2;
            float a0 = accg[im][in][0], a1 = accg[im][in][1];
            float a2 = accg[im][in][2], a3 = accg[im][in][3];
            float h0 = (a0 / (1.f + __expf(-a0))) * accv[im][in][0];
            float h1 = (a1 / (1.f + __expf(-a1))) * accv[im][in][1];
            float h2 = (a2 / (1.f + __expf(-a2))) * accv[im][in][2];
            float h3 = (a3 / (1.f + __expf(-a3))) * accv[im][in][3];
            *reinterpret_cast<__half2*>(g_Hs + ((size_t)g * BATCH + r0) * HID + n) =
                __floats2half2_rn(h0, h1);
            *reinterpret_cast<__half2*>(g_Hs + ((size_t)g * BATCH + r0 + 8) * HID + n) =
                __floats2half2_rn(h2, h3);
        }
    }
}

// ================= phase 2: tok = H @ W2^T (fp16 out) =================
// tile M=128 x N=128 (of DM). 256 threads, 8 warps 4x2 (warp tile 32x64).
// K-chunk 64. Stage = A 16KB + B 16KB = 32KB. 3 stages -> 96KB -> 2 CTAs/SM.
static constexpr int P2_NS   = 3;
static constexpr int P2_STG  = 32 * 1024;
static constexpr int P2_SMEM = P2_NS * P2_STG;

__global__ void __launch_bounds__(256, 2) phase2_kernel() {
    extern __shared__ char smem[];
    const uint32_t sbase = smem_u32(smem);
    const int tid = threadIdx.x;
    const int wid = tid >> 5, lane = tid & 31;
    const int wm = wid >> 1, wn = wid & 1;

    const int g   = blockIdx.z;
    const int nb0 = blockIdx.x * 128;
    const int m0  = blockIdx.y * 128;
    const int nch = HID >> 6;  // 32
    const __half* Ap = g_Hs + ((size_t)g * BATCH + m0) * HID;
    const __half* Bp = g_W2 + ((size_t)g * DM + nb0) * HID;

    float acc[2][8][4];
#pragma unroll
    for (int im = 0; im < 2; im++)
#pragma unroll
        for (int in = 0; in < 8; in++)
#pragma unroll
            for (int q = 0; q < 4; q++) acc[im][in][q] = 0.f;

    auto load_stage = [&](int s, int ch) {
        const uint32_t sb = sbase + (uint32_t)s * P2_STG;
        const int k0 = ch << 6;
#pragma unroll
        for (int j = 0; j < 4; j++) {                 // A: 128x64
            int idx = j * 256 + tid;
            int r = idx >> 3, c = idx & 7;
            cp16(sb + swz((uint32_t)(r * 128 + c * 16)),
                 Ap + (size_t)r * HID + k0 + c * 8);
        }
#pragma unroll
        for (int j = 0; j < 4; j++) {                 // B: 128x64
            int idx = j * 256 + tid;
            int r = idx >> 3, c = idx & 7;
            cp16(sb + 16384 + swz((uint32_t)(r * 128 + c * 16)),
                 Bp + (size_t)r * HID + k0 + c * 8);
        }
        cp_commit();
    };

    auto compute_stage = [&](int s) {
        const uint32_t sb = sbase + (uint32_t)s * P2_STG;
#pragma unroll
        for (int ks = 0; ks < 4; ks++) {
            uint32_t af[2][4];
#pragma unroll
            for (int im = 0; im < 2; im++) {
                int row = wm * 32 + im * 16 + (lane & 15);
                int kk  = ks * 16 + (lane >> 4) * 8;
                ldsm_x4(af[im], sb + swz((uint32_t)(row * 128 + kk * 2)));
            }
            uint32_t bf[4][4];
#pragma unroll
            for (int bp = 0; bp < 4; bp++) {
                int nrow = wn * 64 + bp * 16 + ((lane >> 4) << 3) + (lane & 7);
                int kk   = ks * 16 + ((lane >> 3) & 1) * 8;
                ldsm_x4(bf[bp], sb + 16384 + swz((uint32_t)(nrow * 128 + kk * 2)));
            }
#pragma unroll
            for (int im = 0; im < 2; im++)
#pragma unroll
                for (int in = 0; in < 8; in++) {
                    const int bp = in >> 1, off = (in & 1) * 2;
                    mma16816(acc[im][in], af[im], &bf[bp][off]);
                }
        }
    };

#pragma unroll
    for (int s = 0; s < P2_NS - 1; s++) load_stage(s, s);
    for (int i = 0; i < nch; i++) {
        asm volatile("cp.async.wait_group %0;" :: "n"(P2_NS - 2) : "memory");
        __syncthreads();
        const int nxt = i + P2_NS - 1;
        if (nxt < nch) load_stage(nxt % P2_NS, nxt); else cp_commit();
        compute_stage(i % P2_NS);
    }

    // epilogue: fp16 tokens
#pragma unroll
    for (int im = 0; im < 2; im++) {
        const int r0 = m0 + wm * 32 + im * 16 + (lane >> 2);
#pragma unroll
        for (int in = 0; in < 8; in++) {
            const int n = nb0 + wn * 64 + in * 8 + (lane & 3) * 2;
            __half* t0 = g_tok + ((size_t)g * BATCH + r0) * DM + n;
            __half* t1 = g_tok + ((size_t)g * BATCH + r0 + 8) * DM + n;
            *reinterpret_cast<__half2*>(t0) = __floats2half2_rn(acc[im][in][0], acc[im][in][1]);
            *reinterpret_cast<__half2*>(t1) = __floats2half2_rn(acc[im][in][2], acc[im][in][3]);
        }
    }
}

// ---------------- phase 3: RMS norm + affine + term_embed -> out[b][g][d] ----------------
// Warp-per-row, fully sync-free: shuffle-only reduction, two passes over the
// (L2-hot) row. 8 rows per 256-thread block.
__global__ void __launch_bounds__(256) norm_kernel(const float* __restrict__ nw,
                                                   const float* __restrict__ nb,
                                                   const float* __restrict__ te,
                                                   float* __restrict__ out) {
    const int wid  = threadIdx.x >> 5;
    const int lane = threadIdx.x & 31;
    const int b = blockIdx.x * 8 + wid;
    const int g = blockIdx.y;
    const __half* x = g_tok + ((size_t)g * BATCH + b) * DM;

    // pass 1: sum of squares (4 x uint4 = 32 halves per lane, coalesced)
    float ss = 0.f;
#pragma unroll
    for (int it = 0; it < 4; it++) {
        uint4 raw = *reinterpret_cast<const uint4*>(x + it * 256 + lane * 8);
        const __half2* hp = reinterpret_cast<const __half2*>(&raw);
#pragma unroll
        for (int q = 0; q < 4; q++) {
            float2 f = __half22float2(hp[q]);
            ss += f.x * f.x + f.y * f.y;
        }
    }
#pragma unroll
    for (int o = 16; o > 0; o >>= 1) ss += __shfl_xor_sync(0xffffffffu, ss, o);
    const float inv = rsqrtf(ss * (1.0f / DM) + 1e-5f);

    // pass 2: normalize + affine + embed (re-read row from L1/L2, coalesced float4 out)
    float* orow = out + ((size_t)b * NGRP + g) * DM;
    const float* tep = te + (size_t)g * DM;
#pragma unroll
    for (int it = 0; it < 8; it++) {
        const int c = it * 128 + lane * 4;
        uint2 raw = *reinterpret_cast<const uint2*>(x + c);
        __half2 p0 = *reinterpret_cast<__half2*>(&raw.x);
        __half2 p1 = *reinterpret_cast<__half2*>(&raw.y);
        float2 f0 = __half22float2(p0);
        float2 f1 = __half22float2(p1);
        float4 w  = *reinterpret_cast<const float4*>(nw + c);
        float4 bb = *reinterpret_cast<const float4*>(nb + c);
        float4 e  = *reinterpret_cast<const float4*>(tep + c);
        float4 r;
        r.x = f0.x * inv * w.x + bb.x + e.x;
        r.y = f0.y * inv * w.y + bb.y + e.y;
        r.z = f1.x * inv * w.z + bb.z + e.z;
        r.w = f1.y * inv * w.w + bb.w + e.w;
        __stcs(reinterpret_cast<float4*>(orow + c), r);
    }
}

// ---------------- launch ----------------
extern "C" void kernel_launch(void* const* d_in, const int* in_sizes, int n_in,
                              void* d_out, int out_size) {
    const float* obs   = (const float*)d_in[0];
    const float* w1_g0 = (const float*)d_in[1];
    const float* w3_g0 = (const float*)d_in[2];
    const float* w2_g0 = (const float*)d_in[3];
    const float* w1_r  = (const float*)d_in[4];
    const float* w3_r  = (const float*)d_in[5];
    const float* w2_r  = (const float*)d_in[6];
    const float* nw    = (const float*)d_in[7];
    const float* nb    = (const float*)d_in[8];
    const float* te    = (const float*)d_in[9];
    float* out = (float*)d_out;

    void *p_Xh, *p_W1g0, *p_W3g0, *p_W1r, *p_W3r, *p_W2;
    cudaGetSymbolAddress(&p_Xh,   g_Xh);
    cudaGetSymbolAddress(&p_W1g0, g_W1g0);
    cudaGetSymbolAddress(&p_W3g0, g_W3g0);
    cudaGetSymbolAddress(&p_W1r,  g_W1r);
    cudaGetSymbolAddress(&p_W3r,  g_W3r);
    cudaGetSymbolAddress(&p_W2,   g_W2);

    cudaFuncSetAttribute(phase1_kernel, cudaFuncAttributeMaxDynamicSharedMemorySize, P1_SMEM);
    cudaFuncSetAttribute(phase2_kernel, cudaFuncAttributeMaxDynamicSharedMemorySize, P2_SMEM);

    // Launch #1: ALL fp32->fp16 converts in one sweep
    {
        CvtDesc d;
        int n4[7];
        d.src[0] = obs;    d.dst[0] = (__half*)p_Xh;   n4[0] = (int)((size_t)BATCH * 2048 / 4);
        d.src[1] = w1_g0;  d.dst[1] = (__half*)p_W1g0; n4[1] = (int)((size_t)HID * G0K / 4);
        d.src[2] = w3_g0;  d.dst[2] = (__half*)p_W3g0; n4[2] = (int)((size_t)HID * G0K / 4);
        d.src[3] = w1_r;   d.dst[3] = (__half*)p_W1r;  n4[3] = (int)((size_t)6 * HID * RK / 4);
        d.src[4] = w3_r;   d.dst[4] = (__half*)p_W3r;  n4[4] = (int)((size_t)6 * HID * RK / 4);
        d.src[5] = w2_g0;  d.dst[5] = (__half*)p_W2;   n4[5] = (int)((size_t)DM * HID / 4);
        d.src[6] = w2_r;
        d.dst[6] = (__half*)((char*)p_W2 + (size_t)DM * HID * sizeof(__half));
        n4[6] = (int)((size_t)6 * DM * HID / 4);
        int acc = 0;
        for (int s = 0; s < 7; s++) { acc += n4[s]; d.n4end[s] = acc; }
        cvt_all_kernel<<<(acc + 255) / 256, 256>>>(d);
    }
    // Launch #2: phase 1
    {
        dim3 grid(HID / 64, BATCH / 128, NGRP);
        phase1_kernel<<<grid, 256, P1_SMEM>>>();
    }
    // Launch #3: phase 2
    {
        dim3 grid(DM / 128, BATCH / 128, NGRP);
        phase2_kernel<<<grid, 256, P2_SMEM>>>();
    }
    // Launch #4: norm (warp per row, sync-free)
    {
        dim3 grid(BATCH / 8, NGRP);
        norm_kernel<<<grid, 256>>>(nw, nb, te, out);
    }
    (void)in_sizes; (void)n_in; (void)out_size;
}